// round 10
// baseline (speedup 1.0000x reference)
#include <cuda_runtime.h>
#include <cuda_bf16.h>
#include <math.h>
#include <stdint.h>

#define NX   2048
#define NY   2048
#define DIM  28
#define TM   64
#define TN   64
#define NUM_K_STEPS 14       // K = 224 = 14 * 16
#define RSTRIDE 464          // bytes per smem operand row (448 data + 16 pad)

// smem: A tile [64 rows x 224 bf16] then B tile [64 x 224], both stride 464
#define SMEM_A 0
#define SMEM_B (TM * RSTRIDE)
#define SMEM_TOTAL (SMEM_B + TN * RSTRIDE)   // 59392 bytes
#define STG_STRIDE 72        // floats, epilogue staging stride

// bf16 one-hot row patterns per value v: 8 bf16 (=uint4) per position.
// 1.0f bf16 = 0x3F80, 2.0f = 0x4000
__constant__ uint4 c_patA[8] = {
    {0x00003F80u,0,0,0}, {0x3F800000u,0,0,0}, {0,0x00003F80u,0,0}, {0,0x3F800000u,0,0},
    {0,0,0x00003F80u,0}, {0,0,0x3F800000u,0}, {0,0,0,0x00003F80u}, {0,0,0,0x3F800000u}
};
// B'[t][8d+v] = 2 if v==t, 1 if cls(v)==cls(t), else 0.
// classes: {0,1,2}->1, {3,4,5,6}->0, {7}->2
__constant__ uint4 c_patB[8] = {
    {0x3F804000u, 0x00003F80u, 0u,          0u},
    {0x40003F80u, 0x00003F80u, 0u,          0u},
    {0x3F803F80u, 0x00004000u, 0u,          0u},
    {0u,          0x40000000u, 0x3F803F80u, 0x00003F80u},
    {0u,          0x3F800000u, 0x3F804000u, 0x00003F80u},
    {0u,          0x3F800000u, 0x40003F80u, 0x00003F80u},
    {0u,          0x3F800000u, 0x3F803F80u, 0x00004000u},
    {0u,          0u,          0u,          0x40000000u}
};

__device__ __forceinline__ uint32_t smem_u32(const void* p) {
    uint32_t a;
    asm("{ .reg .u64 t; cvta.to.shared.u64 t, %1; cvt.u32.u64 %0, t; }" : "=r"(a) : "l"(p));
    return a;
}

__device__ __forceinline__ void ldsm_x4(uint32_t& r0, uint32_t& r1, uint32_t& r2, uint32_t& r3,
                                        uint32_t addr) {
    asm volatile("ldmatrix.sync.aligned.m8n8.x4.shared.b16 {%0,%1,%2,%3}, [%4];"
                 : "=r"(r0), "=r"(r1), "=r"(r2), "=r"(r3) : "r"(addr));
}

__device__ __forceinline__ void mma_bf16(float& d0, float& d1, float& d2, float& d3,
                                         uint32_t a0, uint32_t a1, uint32_t a2, uint32_t a3,
                                         uint32_t b0, uint32_t b1) {
    asm volatile("mma.sync.aligned.m16n8k16.row.col.f32.bf16.bf16.f32 "
                 "{%0,%1,%2,%3}, {%4,%5,%6,%7}, {%8,%9}, {%0,%1,%2,%3};"
                 : "+f"(d0), "+f"(d1), "+f"(d2), "+f"(d3)
                 : "r"(a0), "r"(a1), "r"(a2), "r"(a3), "r"(b0), "r"(b1));
}

__global__ __launch_bounds__(256, 3) void gemm_kernel(const int* __restrict__ set_r,
                                                      const int* __restrict__ set_t,
                                                      const float* __restrict__ sigma_ptr,
                                                      float* __restrict__ out)
{
    extern __shared__ char smem[];
    const uint32_t sb = smem_u32(smem);
    const int tid = threadIdx.x;
    const int wid = tid >> 5;
    const int lid = tid & 31;
    const int i0 = blockIdx.y * TM;
    const int j0 = blockIdx.x * TN;

    // ---- pack phase: 256 threads; 2 threads per row (each does 14 positions) ----
    {
        const bool isA = (tid < 128);
        const int local = tid & 127;
        const int row = local & 63;
        const int half = local >> 6;          // 0: d 0..13, 1: d 14..27
        const int* src = isA ? (set_r + (size_t)(i0 + row) * DIM)
                             : (set_t + (size_t)(j0 + row) * DIM);
        uint4 raw[7];
        const uint4* s4 = (const uint4*)src;
#pragma unroll
        for (int k = 0; k < 7; k++) raw[k] = s4[k];
        const int* v = (const int*)raw;

        char* base = smem + (isA ? SMEM_A : SMEM_B) + row * RSTRIDE;
        const uint4* pat = isA ? c_patA : c_patB;
        const int d0 = half * 14;
#pragma unroll
        for (int d = 0; d < 14; d++)
            *(uint4*)(base + (d0 + d) * 16) = pat[v[d0 + d]];
    }
    __syncthreads();

    // ---- mainloop: warp tile 32x16; wm = wid&1 (m block), wn = wid>>1 (n block) ----
    const int wm = wid & 1;
    const int wn = wid >> 1;

    float C[2][2][4];
#pragma unroll
    for (int mf = 0; mf < 2; mf++)
#pragma unroll
        for (int nf = 0; nf < 2; nf++)
#pragma unroll
            for (int q = 0; q < 4; q++) C[mf][nf][q] = 0.0f;

    // precomputed lane address components
    const uint32_t a_row_addr = sb + SMEM_A + (uint32_t)(wm * 32 + (lid & 15)) * RSTRIDE
                              + (uint32_t)(lid >> 4) * 16;
    const uint32_t b_row_addr = sb + SMEM_B
                              + (uint32_t)(wn * 16 + (lid & 7) + (lid >> 4) * 8) * RSTRIDE
                              + (uint32_t)((lid >> 3) & 1) * 16;

#pragma unroll
    for (int k = 0; k < NUM_K_STEPS; k++) {
        const uint32_t kb = (uint32_t)k * 32;

        uint32_t a0[4], a1[4], b[4];
        ldsm_x4(a0[0], a0[1], a0[2], a0[3], a_row_addr + kb);                 // rows wm*32+0..15
        ldsm_x4(a1[0], a1[1], a1[2], a1[3], a_row_addr + 16u * RSTRIDE + kb); // rows wm*32+16..31
        ldsm_x4(b[0], b[1], b[2], b[3], b_row_addr + kb);                     // n rows wn*16+0..15

        mma_bf16(C[0][0][0], C[0][0][1], C[0][0][2], C[0][0][3],
                 a0[0], a0[1], a0[2], a0[3], b[0], b[1]);
        mma_bf16(C[0][1][0], C[0][1][1], C[0][1][2], C[0][1][3],
                 a0[0], a0[1], a0[2], a0[3], b[2], b[3]);
        mma_bf16(C[1][0][0], C[1][0][1], C[1][0][2], C[1][0][3],
                 a1[0], a1[1], a1[2], a1[3], b[0], b[1]);
        mma_bf16(C[1][1][0], C[1][1][1], C[1][1][2], C[1][1][3],
                 a1[0], a1[1], a1[2], a1[3], b[2], b[3]);
    }

    // ---- epilogue: exp, stage to smem, coalesced store ----
    const float sig = *sigma_ptr;
    const float coeff = -1.0f / (1568.0f * sig * sig);   // -(1/28)^2 / (2 sigma^2)

    __syncthreads();   // all ldmatrix reads done before overwriting A region
    float* stg = (float*)smem;

#pragma unroll
    for (int mf = 0; mf < 2; mf++) {
#pragma unroll
        for (int nf = 0; nf < 2; nf++) {
            const int col = wn * 16 + nf * 8 + (lid & 3) * 2;
            const int row0 = wm * 32 + mf * 16 + (lid >> 2);
            float s;
            float2 p;
            s = 56.0f - C[mf][nf][0]; p.x = __expf(coeff * s * s);
            s = 56.0f - C[mf][nf][1]; p.y = __expf(coeff * s * s);
            *(float2*)&stg[row0 * STG_STRIDE + col] = p;
            s = 56.0f - C[mf][nf][2]; p.x = __expf(coeff * s * s);
            s = 56.0f - C[mf][nf][3]; p.y = __expf(coeff * s * s);
            *(float2*)&stg[(row0 + 8) * STG_STRIDE + col] = p;
        }
    }
    __syncthreads();

#pragma unroll
    for (int it = 0; it < 4; it++) {
        const int idx = tid + it * 256;    // 64 rows x 16 float4 chunks
        const int row = idx >> 4;
        const int chunk = idx & 15;
        float4 vv = *(float4*)&stg[row * STG_STRIDE + chunk * 4];
        *(float4*)(out + (size_t)(i0 + row) * NY + j0 + chunk * 4) = vv;
    }
}

extern "C" void kernel_launch(void* const* d_in, const int* in_sizes, int n_in,
                              void* d_out, int out_size)
{
    const int*   set_r = (const int*)d_in[0];
    const int*   set_t = (const int*)d_in[1];
    const float* sigma = (const float*)d_in[2];
    float*       out   = (float*)d_out;

    cudaFuncSetAttribute(gemm_kernel, cudaFuncAttributeMaxDynamicSharedMemorySize, SMEM_TOTAL);
    dim3 grid(NY / TN, NX / TM);
    gemm_kernel<<<grid, 256, SMEM_TOTAL>>>(set_r, set_t, sigma, out);
}